// round 4
// baseline (speedup 1.0000x reference)
#include <cuda_runtime.h>
#include <math_constants.h>

#define NPTS   16384
#define KNN    10
#define NL     11          // K+1 slots per chunk list (self may occupy one)
#define NCHUNK 2
#define CHUNK  (NPTS / NCHUNK)   // 8192
#define TILE   2048
#define QPB    256         // queries per block (== blockDim)

// (-2x, -2y, -2z, x^2+y^2+z^2) per point
__device__ float4 g_pos4[NPTS];
// accumulators: 0 sparsity Σ|op|, 1 opacity Σ(op-.5)^2, 2 scale Σ|s-1|, 3 smooth Σ|Δop|
__device__ float g_acc[4];
// per-chunk candidate lists
__device__ float g_nd[NCHUNK][NPTS][NL];
__device__ int   g_ni[NCHUNK][NPTS][NL];

__device__ __forceinline__ float warp_sum(float v) {
#pragma unroll
    for (int o = 16; o; o >>= 1) v += __shfl_xor_sync(0xffffffffu, v, o);
    return v;
}

__global__ void init_kernel() {
    if (threadIdx.x < 4) g_acc[threadIdx.x] = 0.0f;
}

// precompute pos4 + the three cheap losses
__global__ void prep_kernel(const float* __restrict__ pos,
                            const float* __restrict__ op,
                            const float* __restrict__ sc) {
    int i = blockIdx.x * blockDim.x + threadIdx.x;   // grid covers exactly NPTS
    float x = pos[3 * i + 0], y = pos[3 * i + 1], z = pos[3 * i + 2];
    float sq = fmaf(z, z, fmaf(y, y, x * x));
    g_pos4[i] = make_float4(-2.0f * x, -2.0f * y, -2.0f * z, sq);

    float o  = op[i];
    float sp = fabsf(o);
    float ol = (o - 0.5f) * (o - 0.5f);
    float sl = fabsf(sc[3 * i + 0] - 1.0f)
             + fabsf(sc[3 * i + 1] - 1.0f)
             + fabsf(sc[3 * i + 2] - 1.0f);
    sp = warp_sum(sp);
    ol = warp_sum(ol);
    sl = warp_sum(sl);
    if ((threadIdx.x & 31) == 0) {
        atomicAdd(&g_acc[0], sp);
        atomicAdd(&g_acc[1], ol);
        atomicAdd(&g_acc[2], sl);
    }
}

// thread-per-query KNN over one candidate chunk.
// grid = (NPTS/QPB) * NCHUNK = 128 blocks of 256 threads.
__global__ void __launch_bounds__(QPB) knn_kernel(const float* __restrict__ pos) {
    __shared__ float4 tile[TILE];

    const int chunk = blockIdx.x & (NCHUNK - 1);
    const int q     = (blockIdx.x >> 1) * QPB + threadIdx.x;

    const float qx = pos[3 * q + 0];
    const float qy = pos[3 * q + 1];
    const float qz = pos[3 * q + 2];
    const float qsq = fmaf(qz, qz, fmaf(qy, qy, qx * qx));

    float bd[NL];
    int   bi[NL];
#pragma unroll
    for (int k = 0; k < NL; k++) { bd[k] = CUDART_INF_F; bi[k] = -1; }

    const int base0 = chunk * CHUNK;
    for (int t = 0; t < CHUNK; t += TILE) {
#pragma unroll
        for (int r = 0; r < TILE / QPB; r++)
            tile[r * QPB + threadIdx.x] = g_pos4[base0 + t + r * QPB + threadIdx.x];
        __syncthreads();

#pragma unroll 4
        for (int c = 0; c < TILE; c++) {
            float4 p = tile[c];  // broadcast: all lanes same address
            float d2 = qsq + fmaf(p.x, qx, fmaf(p.y, qy, fmaf(p.z, qz, p.w)));
            if (d2 < bd[NL - 1]) {
                bd[NL - 1] = d2;
                bi[NL - 1] = base0 + t + c;
#pragma unroll
                for (int k = NL - 1; k > 0; --k) {
                    if (bd[k] < bd[k - 1]) {
                        float td = bd[k]; bd[k] = bd[k - 1]; bd[k - 1] = td;
                        int   ti = bi[k]; bi[k] = bi[k - 1]; bi[k - 1] = ti;
                    }
                }
            }
        }
        __syncthreads();
    }

#pragma unroll
    for (int k = 0; k < NL; k++) {
        g_nd[chunk][q][k] = bd[k];
        g_ni[chunk][q][k] = bi[k];
    }
}

// merge the NCHUNK lists per query (filtering self), accumulate smoothness
__global__ void merge_kernel(const float* __restrict__ op) {
    int q = blockIdx.x * blockDim.x + threadIdx.x;

    float bd[KNN];
    int   bi[KNN];
#pragma unroll
    for (int k = 0; k < KNN; k++) { bd[k] = CUDART_INF_F; bi[k] = -1; }

#pragma unroll
    for (int c = 0; c < NCHUNK; c++) {
#pragma unroll
        for (int e = 0; e < NL; e++) {
            float d = g_nd[c][q][e];
            int   j = g_ni[c][q][e];
            if (j >= 0 && j != q && d < bd[KNN - 1]) {
                bd[KNN - 1] = d;
                bi[KNN - 1] = j;
#pragma unroll
                for (int k = KNN - 1; k > 0; --k) {
                    if (bd[k] < bd[k - 1]) {
                        float td = bd[k]; bd[k] = bd[k - 1]; bd[k - 1] = td;
                        int   ti = bi[k]; bi[k] = bi[k - 1]; bi[k - 1] = ti;
                    }
                }
            }
        }
    }

    float oq = op[q];
    float s = 0.0f;
#pragma unroll
    for (int k = 0; k < KNN; k++)
        s += fabsf(oq - op[bi[k]]);

    s = warp_sum(s);
    if ((threadIdx.x & 31) == 0) atomicAdd(&g_acc[3], s);
}

__global__ void final_kernel(float* __restrict__ out) {
    float sparsity  = g_acc[0] * (1.0f / NPTS);
    float opacity   = g_acc[1] * (1.0f / NPTS);
    float scale     = g_acc[2] * (1.0f / (3.0f * NPTS));
    float smooth    = g_acc[3] * (1.0f / ((float)NPTS * KNN));
    out[0] = 0.01f * sparsity + 0.1f * smooth + scale + opacity;
}

extern "C" void kernel_launch(void* const* d_in, const int* in_sizes, int n_in,
                              void* d_out, int out_size) {
    const float* pos = (const float*)d_in[0];
    const float* op  = (const float*)d_in[1];
    const float* sc  = (const float*)d_in[2];
    float* out = (float*)d_out;

    init_kernel<<<1, 32>>>();
    prep_kernel<<<NPTS / 256, 256>>>(pos, op, sc);
    knn_kernel<<<(NPTS / QPB) * NCHUNK, QPB>>>(pos);
    merge_kernel<<<NPTS / 256, 256>>>(op);
    final_kernel<<<1, 1>>>(out);
}